// round 1
// baseline (speedup 1.0000x reference)
#include <cuda_runtime.h>

#define V_TOTAL     8192
#define NODE_DIM    256
#define MAX_DEG     64
#define NUM_SAMPLES 16
#define GROUP_DIM   4
#define N_NODES     100000

// Scratch for linear-branch result L = features[ids] @ W + b   (8 MB)
__device__ float g_L[V_TOTAL * NODE_DIM];

// ---------------------------------------------------------------------------
// Kernel 1: L[v, :] = features[ids[v], :] @ W + b
// Grid: V_TOTAL/64 = 128 blocks, 256 threads.
// Each block computes a 64x256 output tile. Thread j owns output column j for
// all 64 rows (acc[64] in registers). K is chunked into 64-wide smem tiles of
// the gathered A rows; W reads are coalesced and each W element is read once
// per block (128 * 256KB = 32 MB total W traffic).
// ---------------------------------------------------------------------------
__global__ void __launch_bounds__(256) linear_kernel(
    const int*   __restrict__ ids,
    const float* __restrict__ features,
    const float* __restrict__ W,
    const float* __restrict__ b)
{
    __shared__ float As[64][64];   // A chunk: 64 rows x 64 k-elems (16 KB)
    __shared__ int   rowid[64];

    const int tid = threadIdx.x;
    const int m0  = blockIdx.x * 64;

    if (tid < 64) rowid[tid] = ids[m0 + tid];

    float acc[64];
#pragma unroll
    for (int r = 0; r < 64; r++) acc[r] = 0.0f;

    __syncthreads();

    for (int kc = 0; kc < NODE_DIM; kc += 64) {
        // Gather A chunk: 64 rows x 64 floats, coalesced within each row.
#pragma unroll
        for (int idx = tid; idx < 64 * 64; idx += 256) {
            int r = idx >> 6;
            int c = idx & 63;
            As[r][c] = features[(size_t)rowid[r] * NODE_DIM + kc + c];
        }
        __syncthreads();

        for (int d = 0; d < 64; d++) {
            float w = W[(size_t)(kc + d) * NODE_DIM + tid];  // coalesced
#pragma unroll
            for (int r = 0; r < 64; r++)
                acc[r] += As[r][d] * w;                       // As broadcast
        }
        __syncthreads();
    }

    const float bb = b[tid];
#pragma unroll
    for (int r = 0; r < 64; r++)
        g_L[(size_t)(m0 + r) * NODE_DIM + tid] = acc[r] + bb;
}

// ---------------------------------------------------------------------------
// Kernel 2: per-v neighbor scoring + grouped argmin + outputs.
// Grid: 8192 blocks (one per v), 256 threads (8 warps).
// Warp w handles neighbors k = w*8 .. w*8+7. Per neighbor: two coalesced
// LDG.128 (512B each, covering the full 1KB feature row across the warp),
// dot with L[v] (cached in smem / registers), shuffle-reduce, relu.
// Then 16 threads do the grouped first-min argmin and emit outputs.
//
// Output layout (float32):
//   [0,            131072)  sel  (node ids, exact in fp32)
//   [131072,       262144)  att  (all 1.0)
//   [262144,       270336)  numnz
//   [270336,       278528)  numnz (duplicate)
// ---------------------------------------------------------------------------
__global__ void __launch_bounds__(256) sampler_kernel(
    const int*   __restrict__ ids,
    const int*   __restrict__ adj,
    const float* __restrict__ features,
    float*       __restrict__ out)
{
    __shared__ float ls[NODE_DIM];
    __shared__ float scores[MAX_DEG];
    __shared__ int   nbr[MAX_DEG];
    __shared__ float flags[NUM_SAMPLES];

    const int v    = blockIdx.x;
    const int tid  = threadIdx.x;
    const int lane = tid & 31;
    const int w    = tid >> 5;

    const int vid = __ldg(&ids[v]);

    ls[tid] = g_L[(size_t)v * NODE_DIM + tid];
    if (tid < MAX_DEG) nbr[tid] = adj[(size_t)vid * MAX_DEG + tid];
    __syncthreads();

    // Each lane owns elements [lane*4, lane*4+4) and [128+lane*4, 128+lane*4+4)
    const float4 lv0 = ((const float4*)ls)[lane];
    const float4 lv1 = ((const float4*)ls)[lane + 32];

#pragma unroll
    for (int t = 0; t < 8; t++) {
        const int k  = w * 8 + t;
        const int nb = nbr[k];
        const float4* fr = (const float4*)(features + (size_t)nb * NODE_DIM);
        const float4 f0 = __ldg(&fr[lane]);
        const float4 f1 = __ldg(&fr[lane + 32]);

        float s = f0.x * lv0.x + f0.y * lv0.y + f0.z * lv0.z + f0.w * lv0.w
                + f1.x * lv1.x + f1.y * lv1.y + f1.z * lv1.z + f1.w * lv1.w;

#pragma unroll
        for (int off = 16; off > 0; off >>= 1)
            s += __shfl_xor_sync(0xffffffffu, s, off);

        if (lane == 0) scores[k] = fmaxf(s, 0.0f);
    }
    __syncthreads();

    if (tid < NUM_SAMPLES) {
        const int base = tid * GROUP_DIM;
        float m  = scores[base];
        int   bi = 0;
#pragma unroll
        for (int g = 1; g < GROUP_DIM; g++) {
            float sc = scores[base + g];
            if (sc < m) { m = sc; bi = g; }       // strict <  => first min
        }
        const int sid = nbr[base + bi];
        out[(size_t)v * NUM_SAMPLES + tid]                          = (float)sid;
        out[(size_t)V_TOTAL * NUM_SAMPLES + v * NUM_SAMPLES + tid]  = 1.0f;
        flags[tid] = (sid == N_NODES - 1) ? 0.0f : 1.0f;
    }
    __syncthreads();

    if (tid == 0) {
        float nn = 0.0f;
#pragma unroll
        for (int s = 0; s < NUM_SAMPLES; s++) nn += flags[s];
        out[2 * V_TOTAL * NUM_SAMPLES + v]           = nn;
        out[2 * V_TOTAL * NUM_SAMPLES + V_TOTAL + v] = nn;
    }
}

extern "C" void kernel_launch(void* const* d_in, const int* in_sizes, int n_in,
                              void* d_out, int out_size)
{
    const int*   ids      = (const int*)  d_in[0];
    const int*   adj      = (const int*)  d_in[1];
    const float* features = (const float*)d_in[2];
    const float* W        = (const float*)d_in[3];
    const float* b        = (const float*)d_in[4];
    float*       out      = (float*)d_out;

    linear_kernel<<<V_TOTAL / 64, 256>>>(ids, features, W, b);
    sampler_kernel<<<V_TOTAL, 256>>>(ids, adj, features, out);
}

// round 2
// speedup vs baseline: 3.0792x; 3.0792x over previous
#include <cuda_runtime.h>

#define V_TOTAL     8192
#define NODE_DIM    256
#define MAX_DEG     64
#define NUM_SAMPLES 16
#define GROUP_DIM   4
#define N_NODES     100000

#define BM 64
#define BN 64
#define BK 32

// Scratch for linear-branch result L = features[ids] @ W + b   (8 MB)
__device__ float g_L[V_TOTAL * NODE_DIM];

// Packed fp32x2 FMA (Blackwell): d = a*b + d, two fp32 lanes per instruction.
#define FMA2(d, a, b) \
    asm("fma.rn.f32x2 %0, %1, %2, %0;" : "+l"(d) : "l"(a), "l"(b))

static __device__ __forceinline__ unsigned long long dup_f32(float x) {
    unsigned long long r;
    asm("mov.b64 %0, {%1, %1};" : "=l"(r) : "r"(__float_as_uint(x)));
    return r;
}
static __device__ __forceinline__ float2 unpack_f32x2(unsigned long long v) {
    float2 r;
    asm("mov.b64 {%0, %1}, %2;" : "=f"(r.x), "=f"(r.y) : "l"(v));
    return r;
}

// ---------------------------------------------------------------------------
// Kernel 1: L = features[ids] @ W + b   (M=8192, N=256, K=256, fp32)
// Register-tiled SGEMM with packed f32x2 FMAs.
// Grid (128, 4): block computes a 64x64 tile. 256 threads, each a 4x4
// micro-tile (held as 8 packed f32x2 accumulators).
// A tile stored transposed As[k][m] (pad +4) so 4 M-rows load as one LDS.128.
// B tile Bs[k][n] is naturally contiguous in n: an LDS.128 yields two packed
// f32x2 B operands with zero pack cost. Only A needs a dup-pack MOV.
// ---------------------------------------------------------------------------
__global__ void __launch_bounds__(256) linear_kernel(
    const int*   __restrict__ ids,
    const float* __restrict__ features,
    const float* __restrict__ W,
    const float* __restrict__ b)
{
    __shared__ float As[BK][BM + 4];   // transposed A chunk (8.5 KB)
    __shared__ float Bs[BK][BN];       // W chunk (8 KB)
    __shared__ int   rowid[BM];

    const int tid = threadIdx.x;
    const int tx  = tid & 15;          // n-dir: 16 threads * 4 cols
    const int ty  = tid >> 4;          // m-dir: 16 threads * 4 rows
    const int m0  = blockIdx.x * BM;
    const int n0  = blockIdx.y * BN;

    if (tid < BM) rowid[tid] = ids[m0 + tid];

    unsigned long long acc[4][2];
#pragma unroll
    for (int i = 0; i < 4; i++) { acc[i][0] = 0ull; acc[i][1] = 0ull; }

    for (int kc = 0; kc < NODE_DIM; kc += BK) {
        __syncthreads();   // also covers the rowid fill on first iteration

        // Gather A: 64 rows x 32 floats = 512 float4; 2 per thread.
        // Write transposed into As[k][m].
#pragma unroll
        for (int i = tid; i < (BM * BK) / 4; i += 256) {
            const int r  = i >> 3;
            const int c4 = i & 7;
            const float4 v = *(const float4*)
                &features[(size_t)rowid[r] * NODE_DIM + kc + c4 * 4];
            As[c4 * 4 + 0][r] = v.x;
            As[c4 * 4 + 1][r] = v.y;
            As[c4 * 4 + 2][r] = v.z;
            As[c4 * 4 + 3][r] = v.w;
        }

        // Load B: 32 rows x 64 floats = 512 float4; 2 per thread, coalesced.
#pragma unroll
        for (int i = tid; i < (BK * BN) / 4; i += 256) {
            const int kr = i >> 4;
            const int c4 = i & 15;
            *(float4*)&Bs[kr][c4 * 4] = *(const float4*)
                &W[(size_t)(kc + kr) * NODE_DIM + n0 + c4 * 4];
        }
        __syncthreads();

#pragma unroll 8
        for (int k = 0; k < BK; k++) {
            const float4 av = *(const float4*)&As[k][ty * 4];
            const ulonglong2 bv = *(const ulonglong2*)&Bs[k][tx * 4];

            const unsigned long long a0 = dup_f32(av.x);
            const unsigned long long a1 = dup_f32(av.y);
            const unsigned long long a2 = dup_f32(av.z);
            const unsigned long long a3 = dup_f32(av.w);

            FMA2(acc[0][0], a0, bv.x);  FMA2(acc[0][1], a0, bv.y);
            FMA2(acc[1][0], a1, bv.x);  FMA2(acc[1][1], a1, bv.y);
            FMA2(acc[2][0], a2, bv.x);  FMA2(acc[2][1], a2, bv.y);
            FMA2(acc[3][0], a3, bv.x);  FMA2(acc[3][1], a3, bv.y);
        }
    }

    const float4 bias = *(const float4*)&b[n0 + tx * 4];
#pragma unroll
    for (int i = 0; i < 4; i++) {
        const float2 lo = unpack_f32x2(acc[i][0]);
        const float2 hi = unpack_f32x2(acc[i][1]);
        float4 o;
        o.x = lo.x + bias.x;
        o.y = lo.y + bias.y;
        o.z = hi.x + bias.z;
        o.w = hi.y + bias.w;
        const int m = m0 + ty * 4 + i;
        *(float4*)&g_L[(size_t)m * NODE_DIM + n0 + tx * 4] = o;
    }
}

// ---------------------------------------------------------------------------
// Kernel 2: per-v neighbor scoring + grouped argmin + outputs. (unchanged)
// Output layout (float32):
//   [0,            131072)  sel  (node ids, exact in fp32)
//   [131072,       262144)  att  (all 1.0)
//   [262144,       270336)  numnz
//   [270336,       278528)  numnz (duplicate)
// ---------------------------------------------------------------------------
__global__ void __launch_bounds__(256) sampler_kernel(
    const int*   __restrict__ ids,
    const int*   __restrict__ adj,
    const float* __restrict__ features,
    float*       __restrict__ out)
{
    __shared__ float ls[NODE_DIM];
    __shared__ float scores[MAX_DEG];
    __shared__ int   nbr[MAX_DEG];
    __shared__ float flags[NUM_SAMPLES];

    const int v    = blockIdx.x;
    const int tid  = threadIdx.x;
    const int lane = tid & 31;
    const int w    = tid >> 5;

    const int vid = __ldg(&ids[v]);

    ls[tid] = g_L[(size_t)v * NODE_DIM + tid];
    if (tid < MAX_DEG) nbr[tid] = adj[(size_t)vid * MAX_DEG + tid];
    __syncthreads();

    const float4 lv0 = ((const float4*)ls)[lane];
    const float4 lv1 = ((const float4*)ls)[lane + 32];

#pragma unroll
    for (int t = 0; t < 8; t++) {
        const int k  = w * 8 + t;
        const int nb = nbr[k];
        const float4* fr = (const float4*)(features + (size_t)nb * NODE_DIM);
        const float4 f0 = __ldg(&fr[lane]);
        const float4 f1 = __ldg(&fr[lane + 32]);

        float s = f0.x * lv0.x + f0.y * lv0.y + f0.z * lv0.z + f0.w * lv0.w
                + f1.x * lv1.x + f1.y * lv1.y + f1.z * lv1.z + f1.w * lv1.w;

#pragma unroll
        for (int off = 16; off > 0; off >>= 1)
            s += __shfl_xor_sync(0xffffffffu, s, off);

        if (lane == 0) scores[k] = fmaxf(s, 0.0f);
    }
    __syncthreads();

    if (tid < NUM_SAMPLES) {
        const int base = tid * GROUP_DIM;
        float m  = scores[base];
        int   bi = 0;
#pragma unroll
        for (int g = 1; g < GROUP_DIM; g++) {
            float sc = scores[base + g];
            if (sc < m) { m = sc; bi = g; }       // strict <  => first min
        }
        const int sid = nbr[base + bi];
        out[(size_t)v * NUM_SAMPLES + tid]                          = (float)sid;
        out[(size_t)V_TOTAL * NUM_SAMPLES + v * NUM_SAMPLES + tid]  = 1.0f;
        flags[tid] = (sid == N_NODES - 1) ? 0.0f : 1.0f;
    }
    __syncthreads();

    if (tid == 0) {
        float nn = 0.0f;
#pragma unroll
        for (int s = 0; s < NUM_SAMPLES; s++) nn += flags[s];
        out[2 * V_TOTAL * NUM_SAMPLES + v]           = nn;
        out[2 * V_TOTAL * NUM_SAMPLES + V_TOTAL + v] = nn;
    }
}

extern "C" void kernel_launch(void* const* d_in, const int* in_sizes, int n_in,
                              void* d_out, int out_size)
{
    const int*   ids      = (const int*)  d_in[0];
    const int*   adj      = (const int*)  d_in[1];
    const float* features = (const float*)d_in[2];
    const float* W        = (const float*)d_in[3];
    const float* b        = (const float*)d_in[4];
    float*       out      = (float*)d_out;

    linear_kernel<<<dim3(V_TOTAL / BM, NODE_DIM / BN), 256>>>(ids, features, W, b);
    sampler_kernel<<<V_TOTAL, 256>>>(ids, adj, features, out);
}

// round 3
// speedup vs baseline: 3.1965x; 1.0381x over previous
#include <cuda_runtime.h>

#define V_TOTAL     8192
#define NODE_DIM    256
#define MAX_DEG     64
#define NUM_SAMPLES 16
#define GROUP_DIM   4
#define N_NODES     100000

#define BM 64
#define BN 64
#define BK 32
#define NCHUNK (NODE_DIM / BK)   // 8
#define ASTRIDE (BK + 4)         // 36: float4-aligned, conflict-free fills

// Scratch for linear-branch result L = features[ids] @ W + b   (8 MB)
__device__ float g_L[V_TOTAL * NODE_DIM];

// Packed fp32x2 FMA (Blackwell): d = a*b + d, two fp32 lanes per instruction.
#define FMA2(d, a, b) \
    asm("fma.rn.f32x2 %0, %1, %2, %0;" : "+l"(d) : "l"(a), "l"(b))

static __device__ __forceinline__ unsigned long long dup_f32(float x) {
    unsigned long long r;
    asm("mov.b64 %0, {%1, %1};" : "=l"(r) : "r"(__float_as_uint(x)));
    return r;
}
static __device__ __forceinline__ float2 unpack_f32x2(unsigned long long v) {
    float2 r;
    asm("mov.b64 {%0, %1}, %2;" : "=f"(r.x), "=f"(r.y) : "l"(v));
    return r;
}

// ---------------------------------------------------------------------------
// Kernel 1: L = features[ids] @ W + b   (M=8192, N=256, K=256, fp32)
// Register-tiled SGEMM, packed f32x2 FMAs, double-buffered smem (1 sync/chunk).
// Grid (128, 4): 64x64 tile per block, 256 threads, 4x4 micro-tile each.
// As stored [m][k] (pad to 36): float4 fills and broadcast reads are both
// bank-conflict free. B tile [k][n] read as LDS.128 = two packed f32x2.
// ---------------------------------------------------------------------------
__global__ void __launch_bounds__(256) linear_kernel(
    const int*   __restrict__ ids,
    const float* __restrict__ features,
    const float* __restrict__ W,
    const float* __restrict__ b)
{
    __shared__ float As[2][BM][ASTRIDE];   // 18.4 KB
    __shared__ float Bs[2][BK][BN];        // 16 KB
    __shared__ int   rowid[BM];

    const int tid = threadIdx.x;
    const int tx  = tid & 15;          // n-dir: 16 threads * 4 cols
    const int ty  = tid >> 4;          // m-dir: 16 threads * 4 rows
    const int m0  = blockIdx.x * BM;
    const int n0  = blockIdx.y * BN;

    if (tid < BM) rowid[tid] = ids[m0 + tid];
    __syncthreads();

    // Fill-index decomposition (each thread moves 2 float4 of A, 2 of B).
    const int ar  = tid >> 3;          // A row 0..31 (and +32)
    const int ac  = (tid & 7) * 4;     // A col (floats within chunk)
    const int bkr = tid >> 4;          // B k-row 0..15 (and +16)
    const int bc  = (tid & 15) * 4;    // B col

    const size_t rowA0 = (size_t)rowid[ar]      * NODE_DIM;
    const size_t rowA1 = (size_t)rowid[ar + 32] * NODE_DIM;

    unsigned long long acc[4][2];
#pragma unroll
    for (int i = 0; i < 4; i++) { acc[i][0] = 0ull; acc[i][1] = 0ull; }

    // Prefetch + store chunk 0.
    float4 pa0 = *(const float4*)&features[rowA0 + ac];
    float4 pa1 = *(const float4*)&features[rowA1 + ac];
    float4 pb0 = *(const float4*)&W[(size_t)(bkr     ) * NODE_DIM + n0 + bc];
    float4 pb1 = *(const float4*)&W[(size_t)(bkr + 16) * NODE_DIM + n0 + bc];
    *(float4*)&As[0][ar     ][ac] = pa0;
    *(float4*)&As[0][ar + 32][ac] = pa1;
    *(float4*)&Bs[0][bkr     ][bc] = pb0;
    *(float4*)&Bs[0][bkr + 16][bc] = pb1;
    __syncthreads();

    int buf = 0;
#pragma unroll
    for (int c = 0; c < NCHUNK; c++) {
        if (c + 1 < NCHUNK) {
            const int kc = (c + 1) * BK;
            pa0 = *(const float4*)&features[rowA0 + kc + ac];
            pa1 = *(const float4*)&features[rowA1 + kc + ac];
            pb0 = *(const float4*)&W[(size_t)(kc + bkr     ) * NODE_DIM + n0 + bc];
            pb1 = *(const float4*)&W[(size_t)(kc + bkr + 16) * NODE_DIM + n0 + bc];
        }

#pragma unroll
        for (int k = 0; k < BK; k++) {
            const unsigned long long a0 = dup_f32(As[buf][ty * 4 + 0][k]);
            const unsigned long long a1 = dup_f32(As[buf][ty * 4 + 1][k]);
            const unsigned long long a2 = dup_f32(As[buf][ty * 4 + 2][k]);
            const unsigned long long a3 = dup_f32(As[buf][ty * 4 + 3][k]);
            const ulonglong2 bv = *(const ulonglong2*)&Bs[buf][k][tx * 4];

            FMA2(acc[0][0], a0, bv.x);  FMA2(acc[0][1], a0, bv.y);
            FMA2(acc[1][0], a1, bv.x);  FMA2(acc[1][1], a1, bv.y);
            FMA2(acc[2][0], a2, bv.x);  FMA2(acc[2][1], a2, bv.y);
            FMA2(acc[3][0], a3, bv.x);  FMA2(acc[3][1], a3, bv.y);
        }

        if (c + 1 < NCHUNK) {
            *(float4*)&As[buf ^ 1][ar     ][ac] = pa0;
            *(float4*)&As[buf ^ 1][ar + 32][ac] = pa1;
            *(float4*)&Bs[buf ^ 1][bkr     ][bc] = pb0;
            *(float4*)&Bs[buf ^ 1][bkr + 16][bc] = pb1;
        }
        __syncthreads();
        buf ^= 1;
    }

    const float4 bias = *(const float4*)&b[n0 + tx * 4];
#pragma unroll
    for (int i = 0; i < 4; i++) {
        const float2 lo = unpack_f32x2(acc[i][0]);
        const float2 hi = unpack_f32x2(acc[i][1]);
        float4 o;
        o.x = lo.x + bias.x;
        o.y = lo.y + bias.y;
        o.z = hi.x + bias.z;
        o.w = hi.y + bias.w;
        const int m = m0 + ty * 4 + i;
        *(float4*)&g_L[(size_t)m * NODE_DIM + n0 + tx * 4] = o;
    }
}

// ---------------------------------------------------------------------------
// Kernel 2: per-v neighbor scoring + grouped argmin + outputs.
// One block per v, 8 warps. Each warp: 8 neighbors in 2 batches of 4.
// Per batch: 8 LDG.128 issued back-to-back (high MLP), 4 dots, then 4
// interleaved butterfly reductions (independent chains pipeline).
//
// Output layout (float32):
//   [0,            131072)  sel  (node ids, exact in fp32)
//   [131072,       262144)  att  (all 1.0)
//   [262144,       270336)  numnz
//   [270336,       278528)  numnz (duplicate)
// ---------------------------------------------------------------------------
__global__ void __launch_bounds__(256) sampler_kernel(
    const int*   __restrict__ ids,
    const int*   __restrict__ adj,
    const float* __restrict__ features,
    float*       __restrict__ out)
{
    __shared__ float ls[NODE_DIM];
    __shared__ float scores[MAX_DEG];
    __shared__ int   nbr[MAX_DEG];
    __shared__ float flags[NUM_SAMPLES];

    const int v    = blockIdx.x;
    const int tid  = threadIdx.x;
    const int lane = tid & 31;
    const int w    = tid >> 5;

    const int vid = __ldg(&ids[v]);

    ls[tid] = g_L[(size_t)v * NODE_DIM + tid];
    if (tid < MAX_DEG) nbr[tid] = adj[(size_t)vid * MAX_DEG + tid];
    __syncthreads();

    const float4 lv0 = ((const float4*)ls)[lane];
    const float4 lv1 = ((const float4*)ls)[lane + 32];

#pragma unroll
    for (int bstart = 0; bstart < 8; bstart += 4) {
        const int kb = w * 8 + bstart;

        float4 f0[4], f1[4];
#pragma unroll
        for (int t = 0; t < 4; t++) {
            const float4* fr = (const float4*)(features + (size_t)nbr[kb + t] * NODE_DIM);
            f0[t] = __ldg(&fr[lane]);
            f1[t] = __ldg(&fr[lane + 32]);
        }

        float s[4];
#pragma unroll
        for (int t = 0; t < 4; t++) {
            s[t] = f0[t].x * lv0.x + f0[t].y * lv0.y + f0[t].z * lv0.z + f0[t].w * lv0.w
                 + f1[t].x * lv1.x + f1[t].y * lv1.y + f1[t].z * lv1.z + f1[t].w * lv1.w;
        }

#pragma unroll
        for (int off = 16; off > 0; off >>= 1) {
#pragma unroll
            for (int t = 0; t < 4; t++)
                s[t] += __shfl_xor_sync(0xffffffffu, s[t], off);
        }

        if (lane == 0) {
            scores[kb + 0] = fmaxf(s[0], 0.0f);
            scores[kb + 1] = fmaxf(s[1], 0.0f);
            scores[kb + 2] = fmaxf(s[2], 0.0f);
            scores[kb + 3] = fmaxf(s[3], 0.0f);
        }
    }
    __syncthreads();

    if (tid < NUM_SAMPLES) {
        const int base = tid * GROUP_DIM;
        float m  = scores[base];
        int   bi = 0;
#pragma unroll
        for (int g = 1; g < GROUP_DIM; g++) {
            float sc = scores[base + g];
            if (sc < m) { m = sc; bi = g; }       // strict <  => first min
        }
        const int sid = nbr[base + bi];
        out[(size_t)v * NUM_SAMPLES + tid]                          = (float)sid;
        out[(size_t)V_TOTAL * NUM_SAMPLES + v * NUM_SAMPLES + tid]  = 1.0f;
        flags[tid] = (sid == N_NODES - 1) ? 0.0f : 1.0f;
    }
    __syncthreads();

    if (tid == 0) {
        float nn = 0.0f;
#pragma unroll
        for (int s = 0; s < NUM_SAMPLES; s++) nn += flags[s];
        out[2 * V_TOTAL * NUM_SAMPLES + v]           = nn;
        out[2 * V_TOTAL * NUM_SAMPLES + V_TOTAL + v] = nn;
    }
}

extern "C" void kernel_launch(void* const* d_in, const int* in_sizes, int n_in,
                              void* d_out, int out_size)
{
    const int*   ids      = (const int*)  d_in[0];
    const int*   adj      = (const int*)  d_in[1];
    const float* features = (const float*)d_in[2];
    const float* W        = (const float*)d_in[3];
    const float* b        = (const float*)d_in[4];
    float*       out      = (float*)d_out;

    linear_kernel<<<dim3(V_TOTAL / BM, NODE_DIM / BN), 256>>>(ids, features, W, b);
    sampler_kernel<<<V_TOTAL, 256>>>(ids, adj, features, out);
}